// round 1
// baseline (speedup 1.0000x reference)
#include <cuda_runtime.h>
#include <math.h>

#define Bc 64
#define Tn 2048
#define Dd 64
#define Gg 4
#define GDc 16
#define M2 64
#define TP 2047      // T-1
#define CF 256       // Gg*M2
#define ODIM 64
#define SEH 4

// Scratch (device globals; no runtime allocation allowed)
__device__ float g_f256[Bc * TP * CF];     // post-LN features (B,T',256)
__device__ float g_fproj[Bc * TP * ODIM];  // projected features (B,T',64)
__device__ float g_pooled[Bc * ODIM];
__device__ float g_s[Bc * ODIM];

// ---------------------------------------------------------------------------
// Kernel 1: dX -> A (skew) -> expm (s=6, Taylor-9) -> LayerNorm -> g_f256
// One thread per (b, t', g) matrix. Warp g is uniform -> broadcast S reads.
// ---------------------------------------------------------------------------
__global__ __launch_bounds__(128, 2)
void k_expm(const float* __restrict__ x, const float* __restrict__ mask,
            const float* __restrict__ W_dev,
            const float* __restrict__ ln_g, const float* __restrict__ ln_b)
{
    __shared__ float sS[Gg * GDc * M2];   // 4096 floats: S[g][d][64]
    __shared__ float sx[33 * 65];         // x tile rows t0..t0+32, padded
    __shared__ float sG[64], sB[64];

    const int b   = blockIdx.y;
    const int t0  = blockIdx.x * 32;
    const int tid = threadIdx.x;

    // Build skew-symmetric S = tril(W,-1) - tril(W,-1)^T
    for (int idx = tid; idx < Gg * GDc * M2; idx += 128) {
        int j  = idx & 7;
        int i  = (idx >> 3) & 7;
        int gd = idx >> 6;
        float wl = (i > j) ? W_dev[gd * 64 + i * 8 + j] : 0.0f;
        float wu = (j > i) ? W_dev[gd * 64 + j * 8 + i] : 0.0f;
        sS[idx] = wl - wu;
    }
    // x tile (33 rows x 64), clamped at T-1
    for (int idx = tid; idx < 33 * 64; idx += 128) {
        int r = idx >> 6, c = idx & 63;
        int t = t0 + r; if (t > Tn - 1) t = Tn - 1;
        sx[r * 65 + c] = x[(b * Tn + t) * Dd + c];
    }
    if (tid < 64) { sG[tid] = ln_g[tid]; sB[tid] = ln_b[tid]; }
    __syncthreads();

    const int g    = tid >> 5;
    const int lane = tid & 31;
    const int tp   = t0 + lane;
    if (tp >= TP) return;

    const float mval = mask[b * Tn + tp + 1];

    // A = sum_d dX[d] * S[g][d]
    float A[64];
    #pragma unroll
    for (int u = 0; u < 64; u++) A[u] = 0.0f;
    #pragma unroll
    for (int d = 0; d < GDc; d++) {
        float xd = (sx[(lane + 1) * 65 + g * GDc + d] - sx[lane * 65 + g * GDc + d]) * mval;
        const float* Sp = &sS[(g * GDc + d) * 64];
        #pragma unroll
        for (int u = 0; u < 64; u++) A[u] = fmaf(xd, Sp[u], A[u]);
    }
    // scale by 2^-6
    #pragma unroll
    for (int u = 0; u < 64; u++) A[u] *= (1.0f / 64.0f);

    // Taylor: term = A, out = I + A; then k = 2..9
    float Tm[64], O[64];
    #pragma unroll
    for (int u = 0; u < 64; u++) { Tm[u] = A[u]; O[u] = A[u]; }
    #pragma unroll
    for (int i = 0; i < 8; i++) O[i * 9] += 1.0f;

    #pragma unroll 1
    for (int k = 2; k <= 9; k++) {
        float invk = 1.0f / (float)k;
        #pragma unroll
        for (int i = 0; i < 8; i++) {
            float r[8];
            #pragma unroll
            for (int j = 0; j < 8; j++) r[j] = 0.0f;
            #pragma unroll
            for (int kk = 0; kk < 8; kk++) {
                float tv = Tm[i * 8 + kk];
                #pragma unroll
                for (int j = 0; j < 8; j++) r[j] = fmaf(tv, A[kk * 8 + j], r[j]);
            }
            #pragma unroll
            for (int j = 0; j < 8; j++) {
                float nt = r[j] * invk;
                Tm[i * 8 + j] = nt;
                O[i * 8 + j] += nt;
            }
        }
    }

    // 6 squarings: (Tm = O@O; O = Tm@Tm) x3
    #pragma unroll 1
    for (int sq = 0; sq < 3; sq++) {
        #pragma unroll
        for (int i = 0; i < 8; i++) {
            float r[8];
            #pragma unroll
            for (int j = 0; j < 8; j++) r[j] = 0.0f;
            #pragma unroll
            for (int kk = 0; kk < 8; kk++) {
                float tv = O[i * 8 + kk];
                #pragma unroll
                for (int j = 0; j < 8; j++) r[j] = fmaf(tv, O[kk * 8 + j], r[j]);
            }
            #pragma unroll
            for (int j = 0; j < 8; j++) Tm[i * 8 + j] = r[j];
        }
        #pragma unroll
        for (int i = 0; i < 8; i++) {
            float r[8];
            #pragma unroll
            for (int j = 0; j < 8; j++) r[j] = 0.0f;
            #pragma unroll
            for (int kk = 0; kk < 8; kk++) {
                float tv = Tm[i * 8 + kk];
                #pragma unroll
                for (int j = 0; j < 8; j++) r[j] = fmaf(tv, Tm[kk * 8 + j], r[j]);
            }
            #pragma unroll
            for (int j = 0; j < 8; j++) O[i * 8 + j] = r[j];
        }
    }

    // LayerNorm over 64 entries (population variance, two-pass like jnp.var)
    float mu = 0.0f;
    #pragma unroll
    for (int u = 0; u < 64; u++) mu += O[u];
    mu *= (1.0f / 64.0f);
    float vs = 0.0f;
    #pragma unroll
    for (int u = 0; u < 64; u++) { float dv = O[u] - mu; vs = fmaf(dv, dv, vs); }
    vs *= (1.0f / 64.0f);
    float rs = rsqrtf(vs + 1e-5f);

    float* dst = &g_f256[((b * TP + tp) * Gg + g) * 64];
    #pragma unroll
    for (int u = 0; u < 64; u += 4) {
        float4 v;
        v.x = (O[u + 0] - mu) * rs * sG[u + 0] + sB[u + 0];
        v.y = (O[u + 1] - mu) * rs * sG[u + 1] + sB[u + 1];
        v.z = (O[u + 2] - mu) * rs * sG[u + 2] + sB[u + 2];
        v.w = (O[u + 3] - mu) * rs * sG[u + 3] + sB[u + 3];
        *reinterpret_cast<float4*>(dst + u) = v;
    }
}

// ---------------------------------------------------------------------------
// Kernel 2: proj GEMM  (B*TP, 256) @ (256, 64) + bias -> g_fproj
// 64-row tiles, K chunked by 64, 4x4 register blocking per thread.
// ---------------------------------------------------------------------------
__global__ __launch_bounds__(256)
void k_proj(const float* __restrict__ pw, const float* __restrict__ pb)
{
    __shared__ float fs[64][68];   // [row][k] padded
    __shared__ float ws[64][64];   // [k][n]

    const int m0  = blockIdx.x * 64;
    const int tid = threadIdx.x;
    const int tx  = tid & 15;      // n / 4
    const int ty  = tid >> 4;      // m / 4

    float acc[4][4];
    #pragma unroll
    for (int i = 0; i < 4; i++)
        #pragma unroll
        for (int j = 0; j < 4; j++) acc[i][j] = 0.0f;

    for (int kc = 0; kc < 4; kc++) {
        __syncthreads();
        // load f tile: 64 rows x 64 k
        #pragma unroll
        for (int q = tid; q < 1024; q += 256) {
            int row = q >> 4, kq = (q & 15) * 4;
            float4 v = *reinterpret_cast<const float4*>(
                &g_f256[(m0 + row) * CF + kc * 64 + kq]);
            *reinterpret_cast<float4*>(&fs[row][kq]) = v;
        }
        // load w tile: 64 k x 64 n
        #pragma unroll
        for (int q = tid; q < 1024; q += 256) {
            int k = q >> 4, nq = (q & 15) * 4;
            float4 v = *reinterpret_cast<const float4*>(
                &pw[(kc * 64 + k) * ODIM + nq]);
            *reinterpret_cast<float4*>(&ws[k][nq]) = v;
        }
        __syncthreads();

        #pragma unroll 8
        for (int k = 0; k < 64; k++) {
            float4 bv = *reinterpret_cast<const float4*>(&ws[k][tx * 4]);
            float a0 = fs[ty * 4 + 0][k];
            float a1 = fs[ty * 4 + 1][k];
            float a2 = fs[ty * 4 + 2][k];
            float a3 = fs[ty * 4 + 3][k];
            acc[0][0] = fmaf(a0, bv.x, acc[0][0]); acc[0][1] = fmaf(a0, bv.y, acc[0][1]);
            acc[0][2] = fmaf(a0, bv.z, acc[0][2]); acc[0][3] = fmaf(a0, bv.w, acc[0][3]);
            acc[1][0] = fmaf(a1, bv.x, acc[1][0]); acc[1][1] = fmaf(a1, bv.y, acc[1][1]);
            acc[1][2] = fmaf(a1, bv.z, acc[1][2]); acc[1][3] = fmaf(a1, bv.w, acc[1][3]);
            acc[2][0] = fmaf(a2, bv.x, acc[2][0]); acc[2][1] = fmaf(a2, bv.y, acc[2][1]);
            acc[2][2] = fmaf(a2, bv.z, acc[2][2]); acc[2][3] = fmaf(a2, bv.w, acc[2][3]);
            acc[3][0] = fmaf(a3, bv.x, acc[3][0]); acc[3][1] = fmaf(a3, bv.y, acc[3][1]);
            acc[3][2] = fmaf(a3, bv.z, acc[3][2]); acc[3][3] = fmaf(a3, bv.w, acc[3][3]);
        }
    }

    #pragma unroll
    for (int i = 0; i < 4; i++) {
        float4 v;
        v.x = acc[i][0] + pb[tx * 4 + 0];
        v.y = acc[i][1] + pb[tx * 4 + 1];
        v.z = acc[i][2] + pb[tx * 4 + 2];
        v.w = acc[i][3] + pb[tx * 4 + 3];
        *reinterpret_cast<float4*>(&g_fproj[(m0 + ty * 4 + i) * ODIM + tx * 4]) = v;
    }
}

// ---------------------------------------------------------------------------
// Kernel 3a: zero pooled
// ---------------------------------------------------------------------------
__global__ void k_zero()
{
    int i = blockIdx.x * blockDim.x + threadIdx.x;
    if (i < Bc * ODIM) g_pooled[i] = 0.0f;
}

// ---------------------------------------------------------------------------
// Kernel 3: linear interp (2047 -> 2048), h = x + f, write h to out region,
//           accumulate masked pooled sums.
// grid (B, 16), block 256 = 4(t-sub) x 64(d)
// ---------------------------------------------------------------------------
__global__ __launch_bounds__(256)
void k_interp(const float* __restrict__ x, const float* __restrict__ mask,
              float* __restrict__ out)
{
    const int b    = blockIdx.x;
    const int tb   = blockIdx.y * 128;
    const int d    = threadIdx.x & 63;
    const int tsub = threadIdx.x >> 6;
    const float scale = (float)TP / (float)Tn;
    const float* fp = &g_fproj[b * TP * ODIM];

    float lsum = 0.0f;
    #pragma unroll 4
    for (int i = 0; i < 32; i++) {
        int t = tb + tsub * 32 + i;
        float pos = ((float)t + 0.5f) * scale - 0.5f;
        pos = fminf(fmaxf(pos, 0.0f), (float)(TP - 1));
        int i0 = (int)floorf(pos);
        int i1 = min(i0 + 1, TP - 1);
        float w = pos - (float)i0;
        float fv = fp[i0 * ODIM + d] * (1.0f - w) + fp[i1 * ODIM + d] * w;
        float h = x[(b * Tn + t) * Dd + d] + fv;
        out[(b * Tn + t) * Dd + d] = h;
        lsum += h * mask[b * Tn + t];
    }

    __shared__ float red[4][64];
    red[tsub][d] = lsum;
    __syncthreads();
    if (tsub == 0) {
        float s = red[0][d] + red[1][d] + red[2][d] + red[3][d];
        atomicAdd(&g_pooled[b * ODIM + d], s);
    }
}

// ---------------------------------------------------------------------------
// Kernel 4: SE gating. One thread per batch row.
// ---------------------------------------------------------------------------
__global__ void k_se(const float* __restrict__ mask,
                     const float* __restrict__ w1, const float* __restrict__ b1,
                     const float* __restrict__ w2, const float* __restrict__ b2)
{
    int b = threadIdx.x;
    if (b >= Bc) return;

    float denom = 0.0f;
    for (int t = 0; t < Tn; t++) denom += mask[b * Tn + t];
    float inv_denom = 1.0f / denom;

    float hid[SEH];
    #pragma unroll
    for (int h = 0; h < SEH; h++) hid[h] = b1[h];
    for (int d = 0; d < ODIM; d++) {
        float p = g_pooled[b * ODIM + d] * inv_denom;
        #pragma unroll
        for (int h = 0; h < SEH; h++) hid[h] = fmaf(p, w1[d * SEH + h], hid[h]);
    }
    #pragma unroll
    for (int h = 0; h < SEH; h++) {
        float a = hid[h];
        hid[h] = 0.5f * a * (1.0f + erff(a * 0.70710678118654752440f));
    }
    for (int o = 0; o < ODIM; o++) {
        float a = b2[o];
        #pragma unroll
        for (int h = 0; h < SEH; h++) a = fmaf(hid[h], w2[h * ODIM + o], a);
        g_s[b * ODIM + o] = 1.0f / (1.0f + expf(-a));
    }
}

// ---------------------------------------------------------------------------
// Kernel 5: out = h * s + x  (h already in out region), plus mask tail copy.
// ---------------------------------------------------------------------------
__global__ void k_final(const float* __restrict__ x, const float* __restrict__ mask,
                        float* __restrict__ out, int out_size)
{
    const int N1 = Bc * Tn * Dd;
    int idx = blockIdx.x * blockDim.x + threadIdx.x;
    if (idx < N1) {
        int d  = idx & 63;
        int bt = idx >> 6;
        int b  = bt >> 11;   // T = 2048
        float h = out[idx];
        out[idx] = fmaf(h, g_s[b * ODIM + d], x[idx]);
    } else if (idx < out_size) {
        int mi = idx - N1;
        if (mi < Bc * Tn) out[idx] = mask[mi];
    }
}

// ---------------------------------------------------------------------------
extern "C" void kernel_launch(void* const* d_in, const int* in_sizes, int n_in,
                              void* d_out, int out_size)
{
    const float* x     = (const float*)d_in[0];
    const float* mask  = (const float*)d_in[1];
    const float* W_dev = (const float*)d_in[2];
    const float* ln_g  = (const float*)d_in[3];
    const float* ln_b  = (const float*)d_in[4];
    const float* pw    = (const float*)d_in[5];
    const float* pb    = (const float*)d_in[6];
    const float* se_w1 = (const float*)d_in[7];
    const float* se_b1 = (const float*)d_in[8];
    const float* se_w2 = (const float*)d_in[9];
    const float* se_b2 = (const float*)d_in[10];
    float* out = (float*)d_out;

    k_expm<<<dim3((TP + 31) / 32, Bc), 128>>>(x, mask, W_dev, ln_g, ln_b);
    k_proj<<<(Bc * TP) / 64, 256>>>(pw, pb);
    k_zero<<<(Bc * ODIM + 255) / 256, 256>>>();
    k_interp<<<dim3(Bc, 16), 256>>>(x, mask, out);
    k_se<<<1, 64>>>(mask, se_w1, se_b1, se_w2, se_b2);

    int total = out_size;
    k_final<<<(total + 255) / 256, 256>>>(x, mask, out, out_size);
}

// round 2
// speedup vs baseline: 1.0130x; 1.0130x over previous
#include <cuda_runtime.h>
#include <math.h>

#define Bc 64
#define Tn 2048
#define Dd 64
#define Gg 4
#define GDc 16
#define M2 64
#define TP 2047      // T-1
#define CF 256       // Gg*M2
#define ODIM 64
#define SEH 4

// Scratch (device globals; no runtime allocation allowed)
__device__ float g_f256[Bc * TP * CF];     // post-LN features (B,T',256)
__device__ float g_fproj[Bc * TP * ODIM];  // projected features (B,T',64)
__device__ float g_pooled[Bc * ODIM];
__device__ float g_s[Bc * ODIM];

// 8x8 matmul: Z = X*Y (Z must not alias X or Y)
__device__ __forceinline__ void mm88(const float (&X)[64], const float (&Y)[64],
                                     float (&Z)[64])
{
    #pragma unroll
    for (int i = 0; i < 8; i++) {
        float r[8];
        #pragma unroll
        for (int j = 0; j < 8; j++) r[j] = 0.0f;
        #pragma unroll
        for (int kk = 0; kk < 8; kk++) {
            float t = X[i * 8 + kk];
            #pragma unroll
            for (int j = 0; j < 8; j++) r[j] = fmaf(t, Y[kk * 8 + j], r[j]);
        }
        #pragma unroll
        for (int j = 0; j < 8; j++) Z[i * 8 + j] = r[j];
    }
}

// Z += X*Y, in-place safe when Z aliases neither X nor Y (row-local updates)
__device__ __forceinline__ void mm88_acc(const float (&X)[64], const float (&Y)[64],
                                         float (&Z)[64])
{
    #pragma unroll
    for (int i = 0; i < 8; i++) {
        float r[8];
        #pragma unroll
        for (int j = 0; j < 8; j++) r[j] = 0.0f;
        #pragma unroll
        for (int kk = 0; kk < 8; kk++) {
            float t = X[i * 8 + kk];
            #pragma unroll
            for (int j = 0; j < 8; j++) r[j] = fmaf(t, Y[kk * 8 + j], r[j]);
        }
        #pragma unroll
        for (int j = 0; j < 8; j++) Z[i * 8 + j] += r[j];
    }
}

// ---------------------------------------------------------------------------
// Kernel 1: dX -> A (skew) -> expm (s=4, Paterson-Stockmeyer deg-6) -> LN
// One thread per (b, t', g) matrix. Warp g is uniform -> broadcast S reads.
// ---------------------------------------------------------------------------
__global__ __launch_bounds__(128, 2)
void k_expm(const float* __restrict__ x, const float* __restrict__ mask,
            const float* __restrict__ W_dev,
            const float* __restrict__ ln_g, const float* __restrict__ ln_b)
{
    __shared__ float sS[Gg * GDc * M2];   // 4096 floats: S[g][d][64]
    __shared__ float sx[33 * 65];         // x tile rows t0..t0+32, padded
    __shared__ float sG[64], sB[64];

    const int b   = blockIdx.y;
    const int t0  = blockIdx.x * 32;
    const int tid = threadIdx.x;

    // Build skew-symmetric S = tril(W,-1) - tril(W,-1)^T
    for (int idx = tid; idx < Gg * GDc * M2; idx += 128) {
        int j  = idx & 7;
        int i  = (idx >> 3) & 7;
        int gd = idx >> 6;
        float wl = (i > j) ? W_dev[gd * 64 + i * 8 + j] : 0.0f;
        float wu = (j > i) ? W_dev[gd * 64 + j * 8 + i] : 0.0f;
        sS[idx] = wl - wu;
    }
    // x tile (33 rows x 64), clamped at T-1
    for (int idx = tid; idx < 33 * 64; idx += 128) {
        int r = idx >> 6, c = idx & 63;
        int t = t0 + r; if (t > Tn - 1) t = Tn - 1;
        sx[r * 65 + c] = x[(b * Tn + t) * Dd + c];
    }
    if (tid < 64) { sG[tid] = ln_g[tid]; sB[tid] = ln_b[tid]; }
    __syncthreads();

    const int g    = tid >> 5;
    const int lane = tid & 31;
    const int tp   = t0 + lane;
    if (tp >= TP) return;

    const float mval = mask[b * Tn + tp + 1];

    // dX, with 2^-s (s=4) scaling folded in
    float dx[GDc];
    #pragma unroll
    for (int d = 0; d < GDc; d++) {
        dx[d] = (sx[(lane + 1) * 65 + g * GDc + d] - sx[lane * 65 + g * GDc + d])
                * mval * (1.0f / 16.0f);
    }

    // A = sum_d dx[d] * S[g][d]  (vectorized smem reads)
    float A[64];
    #pragma unroll
    for (int u = 0; u < 64; u++) A[u] = 0.0f;
    #pragma unroll
    for (int d = 0; d < GDc; d++) {
        float xd = dx[d];
        const float4* Sp4 = reinterpret_cast<const float4*>(&sS[(g * GDc + d) * 64]);
        #pragma unroll
        for (int u4 = 0; u4 < 16; u4++) {
            float4 s4 = Sp4[u4];
            A[u4 * 4 + 0] = fmaf(xd, s4.x, A[u4 * 4 + 0]);
            A[u4 * 4 + 1] = fmaf(xd, s4.y, A[u4 * 4 + 1]);
            A[u4 * 4 + 2] = fmaf(xd, s4.z, A[u4 * 4 + 2]);
            A[u4 * 4 + 3] = fmaf(xd, s4.w, A[u4 * 4 + 3]);
        }
    }

    // Paterson-Stockmeyer degree-6 Taylor of exp(A):
    // A2 = A*A ; A3 = A2*A
    float T2[64], T3[64];
    mm88(A, A, T2);
    mm88(T2, A, T3);

    // low -> A ; q -> T2 (single elementwise pass, both from pre-overwrite scalars)
    #pragma unroll
    for (int i = 0; i < 8; i++) {
        #pragma unroll
        for (int j = 0; j < 8; j++) {
            int u = i * 8 + j;
            float a = A[u], a2 = T2[u], a3 = T3[u];
            float low = a + a2 * 0.5f + a3 * (1.0f / 6.0f);
            if (i == j) low += 1.0f;
            A[u]  = low;
            T2[u] = a * (1.0f / 24.0f) + a2 * (1.0f / 120.0f) + a3 * (1.0f / 720.0f);
        }
    }
    // P = low + A3*q   (accumulate into A)
    mm88_acc(T3, T2, A);

    // 4 squarings: T2 = A*A ; A = T2*T2 (x2)
    #pragma unroll 1
    for (int sq = 0; sq < 2; sq++) {
        mm88(A, A, T2);
        mm88(T2, T2, A);
    }

    // LayerNorm over 64 entries
    float mu = 0.0f;
    #pragma unroll
    for (int u = 0; u < 64; u++) mu += A[u];
    mu *= (1.0f / 64.0f);
    float vs = 0.0f;
    #pragma unroll
    for (int u = 0; u < 64; u++) { float dv = A[u] - mu; vs = fmaf(dv, dv, vs); }
    vs *= (1.0f / 64.0f);
    float rs = rsqrtf(vs + 1e-5f);

    float* dst = &g_f256[((b * TP + tp) * Gg + g) * 64];
    #pragma unroll
    for (int u = 0; u < 64; u += 4) {
        float4 v;
        v.x = (A[u + 0] - mu) * rs * sG[u + 0] + sB[u + 0];
        v.y = (A[u + 1] - mu) * rs * sG[u + 1] + sB[u + 1];
        v.z = (A[u + 2] - mu) * rs * sG[u + 2] + sB[u + 2];
        v.w = (A[u + 3] - mu) * rs * sG[u + 3] + sB[u + 3];
        *reinterpret_cast<float4*>(dst + u) = v;
    }
}

// ---------------------------------------------------------------------------
// Kernel 2: proj GEMM  (B*TP, 256) @ (256, 64) + bias -> g_fproj
// 64-row tiles, 128 threads, 4m x 8n register blocking.
// ---------------------------------------------------------------------------
__global__ __launch_bounds__(128)
void k_proj(const float* __restrict__ pw, const float* __restrict__ pb)
{
    __shared__ float fs[64][68];   // [row][k] padded
    __shared__ float ws[64][64];   // [k][n]

    const int m0  = blockIdx.x * 64;
    const int tid = threadIdx.x;
    const int tx  = tid & 7;       // n / 8
    const int ty  = tid >> 3;      // m / 4

    float acc[4][8];
    #pragma unroll
    for (int i = 0; i < 4; i++)
        #pragma unroll
        for (int j = 0; j < 8; j++) acc[i][j] = 0.0f;

    for (int kc = 0; kc < 4; kc++) {
        __syncthreads();
        // f tile: 64 rows x 64 k
        #pragma unroll
        for (int q = tid; q < 1024; q += 128) {
            int row = q >> 4, kq = (q & 15) * 4;
            float4 v = *reinterpret_cast<const float4*>(
                &g_f256[(m0 + row) * CF + kc * 64 + kq]);
            *reinterpret_cast<float4*>(&fs[row][kq]) = v;
        }
        // w tile: 64 k x 64 n
        #pragma unroll
        for (int q = tid; q < 1024; q += 128) {
            int k = q >> 4, nq = (q & 15) * 4;
            float4 v = *reinterpret_cast<const float4*>(
                &pw[(kc * 64 + k) * ODIM + nq]);
            *reinterpret_cast<float4*>(&ws[k][nq]) = v;
        }
        __syncthreads();

        #pragma unroll 8
        for (int k = 0; k < 64; k++) {
            float4 b0 = *reinterpret_cast<const float4*>(&ws[k][tx * 8]);
            float4 b1 = *reinterpret_cast<const float4*>(&ws[k][tx * 8 + 4]);
            #pragma unroll
            for (int i = 0; i < 4; i++) {
                float a = fs[ty * 4 + i][k];
                acc[i][0] = fmaf(a, b0.x, acc[i][0]);
                acc[i][1] = fmaf(a, b0.y, acc[i][1]);
                acc[i][2] = fmaf(a, b0.z, acc[i][2]);
                acc[i][3] = fmaf(a, b0.w, acc[i][3]);
                acc[i][4] = fmaf(a, b1.x, acc[i][4]);
                acc[i][5] = fmaf(a, b1.y, acc[i][5]);
                acc[i][6] = fmaf(a, b1.z, acc[i][6]);
                acc[i][7] = fmaf(a, b1.w, acc[i][7]);
            }
        }
    }

    float4 bias0 = *reinterpret_cast<const float4*>(&pb[tx * 8]);
    float4 bias1 = *reinterpret_cast<const float4*>(&pb[tx * 8 + 4]);
    #pragma unroll
    for (int i = 0; i < 4; i++) {
        float4 v0, v1;
        v0.x = acc[i][0] + bias0.x; v0.y = acc[i][1] + bias0.y;
        v0.z = acc[i][2] + bias0.z; v0.w = acc[i][3] + bias0.w;
        v1.x = acc[i][4] + bias1.x; v1.y = acc[i][5] + bias1.y;
        v1.z = acc[i][6] + bias1.z; v1.w = acc[i][7] + bias1.w;
        float* o = &g_fproj[(m0 + ty * 4 + i) * ODIM + tx * 8];
        *reinterpret_cast<float4*>(o)     = v0;
        *reinterpret_cast<float4*>(o + 4) = v1;
    }
}

// ---------------------------------------------------------------------------
// Kernel 3a: zero pooled
// ---------------------------------------------------------------------------
__global__ void k_zero()
{
    int i = blockIdx.x * blockDim.x + threadIdx.x;
    if (i < Bc * ODIM) g_pooled[i] = 0.0f;
}

// ---------------------------------------------------------------------------
// Kernel 3: linear interp (2047 -> 2048), h = x + f, write h to out region,
//           accumulate masked pooled sums.
// ---------------------------------------------------------------------------
__global__ __launch_bounds__(256)
void k_interp(const float* __restrict__ x, const float* __restrict__ mask,
              float* __restrict__ out)
{
    const int b    = blockIdx.x;
    const int tb   = blockIdx.y * 128;
    const int d    = threadIdx.x & 63;
    const int tsub = threadIdx.x >> 6;
    const float scale = (float)TP / (float)Tn;
    const float* fp = &g_fproj[b * TP * ODIM];

    float lsum = 0.0f;
    #pragma unroll 4
    for (int i = 0; i < 32; i++) {
        int t = tb + tsub * 32 + i;
        float pos = ((float)t + 0.5f) * scale - 0.5f;
        pos = fminf(fmaxf(pos, 0.0f), (float)(TP - 1));
        int i0 = (int)floorf(pos);
        int i1 = min(i0 + 1, TP - 1);
        float w = pos - (float)i0;
        float fv = fp[i0 * ODIM + d] * (1.0f - w) + fp[i1 * ODIM + d] * w;
        float h = x[(b * Tn + t) * Dd + d] + fv;
        out[(b * Tn + t) * Dd + d] = h;
        lsum += h * mask[b * Tn + t];
    }

    __shared__ float red[4][64];
    red[tsub][d] = lsum;
    __syncthreads();
    if (tsub == 0) {
        float s = red[0][d] + red[1][d] + red[2][d] + red[3][d];
        atomicAdd(&g_pooled[b * ODIM + d], s);
    }
}

// ---------------------------------------------------------------------------
// Kernel 4: SE gating. One thread per batch row.
// ---------------------------------------------------------------------------
__global__ void k_se(const float* __restrict__ mask,
                     const float* __restrict__ w1, const float* __restrict__ b1,
                     const float* __restrict__ w2, const float* __restrict__ b2)
{
    int b = threadIdx.x;
    if (b >= Bc) return;

    float denom = 0.0f;
    for (int t = 0; t < Tn; t++) denom += mask[b * Tn + t];
    float inv_denom = 1.0f / denom;

    float hid[SEH];
    #pragma unroll
    for (int h = 0; h < SEH; h++) hid[h] = b1[h];
    for (int d = 0; d < ODIM; d++) {
        float p = g_pooled[b * ODIM + d] * inv_denom;
        #pragma unroll
        for (int h = 0; h < SEH; h++) hid[h] = fmaf(p, w1[d * SEH + h], hid[h]);
    }
    #pragma unroll
    for (int h = 0; h < SEH; h++) {
        float a = hid[h];
        hid[h] = 0.5f * a * (1.0f + erff(a * 0.70710678118654752440f));
    }
    for (int o = 0; o < ODIM; o++) {
        float a = b2[o];
        #pragma unroll
        for (int h = 0; h < SEH; h++) a = fmaf(hid[h], w2[h * ODIM + o], a);
        g_s[b * ODIM + o] = 1.0f / (1.0f + expf(-a));
    }
}

// ---------------------------------------------------------------------------
// Kernel 5: out = h * s + x  (h already in out region), plus mask tail copy.
// ---------------------------------------------------------------------------
__global__ void k_final(const float* __restrict__ x, const float* __restrict__ mask,
                        float* __restrict__ out, int out_size)
{
    const int N1 = Bc * Tn * Dd;
    int idx = blockIdx.x * blockDim.x + threadIdx.x;
    if (idx < N1) {
        int d  = idx & 63;
        int bt = idx >> 6;
        int b  = bt >> 11;   // T = 2048
        float h = out[idx];
        out[idx] = fmaf(h, g_s[b * ODIM + d], x[idx]);
    } else if (idx < out_size) {
        int mi = idx - N1;
        if (mi < Bc * Tn) out[idx] = mask[mi];
    }
}

// ---------------------------------------------------------------------------
extern "C" void kernel_launch(void* const* d_in, const int* in_sizes, int n_in,
                              void* d_out, int out_size)
{
    const float* x     = (const float*)d_in[0];
    const float* mask  = (const float*)d_in[1];
    const float* W_dev = (const float*)d_in[2];
    const float* ln_g  = (const float*)d_in[3];
    const float* ln_b  = (const float*)d_in[4];
    const float* pw    = (const float*)d_in[5];
    const float* pb    = (const float*)d_in[6];
    const float* se_w1 = (const float*)d_in[7];
    const float* se_b1 = (const float*)d_in[8];
    const float* se_w2 = (const float*)d_in[9];
    const float* se_b2 = (const float*)d_in[10];
    float* out = (float*)d_out;

    k_expm<<<dim3((TP + 31) / 32, Bc), 128>>>(x, mask, W_dev, ln_g, ln_b);
    k_proj<<<(Bc * TP) / 64, 128>>>(pw, pb);
    k_zero<<<(Bc * ODIM + 255) / 256, 256>>>();
    k_interp<<<dim3(Bc, 16), 256>>>(x, mask, out);
    k_se<<<1, 64>>>(mask, se_w1, se_b1, se_w2, se_b2);

    k_final<<<(out_size + 255) / 256, 256>>>(x, mask, out, out_size);
}